// round 4
// baseline (speedup 1.0000x reference)
#include <cuda_runtime.h>
#include <cstdint>
#include <math_constants.h>

#define BB   32
#define LQ   512
#define LK   2048
#define DD   768
#define D4   (DD/4)     // 192
#define NQC  16
#define QPC  (LQ/NQC)   // 32
#define NCH  8
#define KCH  (LK/NCH)   // 256
#define SUB  16
#define NSUB (KCH/SUB)  // 16
#define TPB  256
#define ESPL 24
#define EPB  (DD/ESPL)  // 32

// scratch (device globals — no allocation allowed)
__device__ float g_sp  [BB*NQC*DD];
__device__ float g_ssum[BB*DD];
__device__ float g_qsum[BB*DD];
__device__ float g_wp  [ESPL*BB*DD];
__device__ float g_pm  [BB*NCH];
__device__ float g_pl  [BB*NCH];
__device__ float g_pacc[BB*NCH*DD];
__device__ float g_vin [BB*DD];
__device__ int   g_cnt_s[BB];   // zero-init; reset after each use
__device__ int   g_cnt_a[BB];   // zero-init; reset after each use

// ---------------- K1: row-sums of sentence_rep (fused partial + reduce) ----------------
// grid (NQC, BB), 192 threads, float4 lanes.
__global__ void k_ssum(const float* __restrict__ sr) {
    int qc = blockIdx.x, b = blockIdx.y, t = threadIdx.x;   // t < 192
    const float4* p = reinterpret_cast<const float4*>(sr) +
                      ((size_t)b*LQ + (size_t)qc*QPC)*D4 + t;
    float4 a = make_float4(0.f,0.f,0.f,0.f);
#pragma unroll
    for (int q = 0; q < QPC; q++) {
        float4 v = p[(size_t)q*D4];
        a.x += v.x; a.y += v.y; a.z += v.z; a.w += v.w;
    }
    reinterpret_cast<float4*>(g_sp)[(b*NQC + qc)*D4 + t] = a;

    __threadfence();
    __syncthreads();
    __shared__ int s_last;
    if (t == 0) s_last = (atomicAdd(&g_cnt_s[b], 1) == NQC-1);
    __syncthreads();
    if (s_last) {
        if (t == 0) g_cnt_s[b] = 0;
        __threadfence();
        float4 r = make_float4(0.f,0.f,0.f,0.f);
#pragma unroll
        for (int c = 0; c < NQC; c++) {
            float4 v = reinterpret_cast<const float4*>(g_sp)[(b*NQC + c)*D4 + t];
            r.x += v.x; r.y += v.y; r.z += v.z; r.w += v.w;
        }
        reinterpret_cast<float4*>(g_ssum)[b*D4 + t] = r;
    }
}

// ---------------- K2: q_sum[b,e] = s_sum[b,:]·Wq[e,:] + 512*bq[e] ----------------
__global__ void k_qsum(const float* __restrict__ Wq, const float* __restrict__ bq) {
    int e = blockIdx.x;
    __shared__ float wrow[DD];
    for (int i = threadIdx.x; i < D4; i += 128)
        reinterpret_cast<float4*>(wrow)[i] =
            reinterpret_cast<const float4*>(Wq + (size_t)e*DD)[i];
    __syncthreads();
    int warp = threadIdx.x >> 5, lane = threadIdx.x & 31;
    float be = 512.0f * bq[e];
    const float4* w4 = reinterpret_cast<const float4*>(wrow);
    for (int b = warp; b < BB; b += 4) {
        const float4* s4 = reinterpret_cast<const float4*>(g_ssum + b*DD);
        float acc = 0.f;
#pragma unroll
        for (int i = 0; i < D4/32; i++) {
            float4 w = w4[lane + 32*i], s = s4[lane + 32*i];
            acc = fmaf(w.x, s.x, acc); acc = fmaf(w.y, s.y, acc);
            acc = fmaf(w.z, s.z, acc); acc = fmaf(w.w, s.w, acc);
        }
#pragma unroll
        for (int o = 16; o; o >>= 1) acc += __shfl_xor_sync(0xffffffffu, acc, o);
        if (lane == 0) g_qsum[b*DD + e] = acc + be;
    }
}

// ---------------- K3: w partials, float4 over d ----------------
// grid (BB/2, ESPL) = 384 blocks, 192 threads
__global__ void k_w(const float* __restrict__ Wk) {
    int b0 = blockIdx.x * 2;
    int z  = blockIdx.y;
    int e0 = z * EPB;
    int t  = threadIdx.x;   // t < 192 -> d = 4t..4t+3
    __shared__ float qs[2*EPB];
    if (t < 2*EPB)
        qs[t] = g_qsum[(b0 + t/EPB)*DD + e0 + (t % EPB)];
    __syncthreads();
    const float4* Wk4 = reinterpret_cast<const float4*>(Wk);
    float4 a0 = make_float4(0.f,0.f,0.f,0.f);
    float4 a1 = make_float4(0.f,0.f,0.f,0.f);
#pragma unroll 8
    for (int e = 0; e < EPB; e++) {
        float4 wk = Wk4[(size_t)(e0 + e)*D4 + t];
        float q0 = qs[e], q1 = qs[EPB + e];
        a0.x = fmaf(wk.x, q0, a0.x); a0.y = fmaf(wk.y, q0, a0.y);
        a0.z = fmaf(wk.z, q0, a0.z); a0.w = fmaf(wk.w, q0, a0.w);
        a1.x = fmaf(wk.x, q1, a1.x); a1.y = fmaf(wk.y, q1, a1.y);
        a1.z = fmaf(wk.z, q1, a1.z); a1.w = fmaf(wk.w, q1, a1.w);
    }
    reinterpret_cast<float4*>(g_wp)[(z*BB + b0+0)*D4 + t] = a0;
    reinterpret_cast<float4*>(g_wp)[(z*BB + b0+1)*D4 + t] = a1;
}

// ---------------- K4: fused scores + online softmax + weighted V-sum + combine ----------
// grid = (NCH, BB) = 256 blocks, 2 blocks/SM.
#define SMEM_FLOATS (2*SUB*DD + DD + 2*SUB + 4)

__global__ void __launch_bounds__(TPB) k_attn(const float* __restrict__ cr) {
    int b = blockIdx.y, ch = blockIdx.x;
    int tid = threadIdx.x, warp = tid >> 5, lane = tid & 31;
    extern __shared__ float sm[];
    float* buf0 = sm;
    float* buf1 = sm + SUB*DD;
    float* ws   = sm + 2*SUB*DD;
    float* ss   = ws + DD;
    float* ps   = ss + SUB;
    float* ml   = ps + SUB;   // [0]=m, [1]=l, [2]=scale

    const float* base = cr + ((size_t)b*LK + (size_t)ch*KCH)*DD;

    // issue load of subchunk 0
    {
        uint32_t sa = (uint32_t)__cvta_generic_to_shared(buf0);
        const float4* g = reinterpret_cast<const float4*>(base);
#pragma unroll
        for (int i = 0; i < (SUB*DD/4)/TPB; i++)
            asm volatile("cp.async.cg.shared.global [%0], [%1], 16;\n"
                :: "r"(sa + (uint32_t)((tid + i*TPB)*16)), "l"(g + tid + i*TPB));
        asm volatile("cp.async.commit_group;\n");
    }
    // ws = sum of e-split partials (L2-resident), float4 lanes
    if (tid < D4) {
        float4 a = make_float4(0.f,0.f,0.f,0.f);
#pragma unroll
        for (int z = 0; z < ESPL; z++) {
            float4 v = reinterpret_cast<const float4*>(g_wp)[(z*BB + b)*D4 + tid];
            a.x += v.x; a.y += v.y; a.z += v.z; a.w += v.w;
        }
        reinterpret_cast<float4*>(ws)[tid] = a;
    }
    if (tid == 0) { ml[0] = -CUDART_INF_F; ml[1] = 0.0f; }

    float4 acc = make_float4(0.f, 0.f, 0.f, 0.f);
    const float4* ws4 = reinterpret_cast<const float4*>(ws);

    for (int sc = 0; sc < NSUB; sc++) {
        if (sc + 1 < NSUB) {
            float* nb = ((sc + 1) & 1) ? buf1 : buf0;
            uint32_t sa = (uint32_t)__cvta_generic_to_shared(nb);
            const float4* g = reinterpret_cast<const float4*>(base + (size_t)(sc+1)*SUB*DD);
#pragma unroll
            for (int i = 0; i < (SUB*DD/4)/TPB; i++)
                asm volatile("cp.async.cg.shared.global [%0], [%1], 16;\n"
                    :: "r"(sa + (uint32_t)((tid + i*TPB)*16)), "l"(g + tid + i*TPB));
            asm volatile("cp.async.commit_group;\n");
            asm volatile("cp.async.wait_group 1;\n");
        } else {
            asm volatile("cp.async.wait_group 0;\n");
        }
        __syncthreads();
        float* cb = (sc & 1) ? buf1 : buf0;
        const float4* cb4 = reinterpret_cast<const float4*>(cb);

        // scores: 2 k per warp, vectorized warp-reduced dot with w
#pragma unroll
        for (int j = 0; j < SUB/8; j++) {
            int k = warp*(SUB/8) + j;
            const float4* row4 = reinterpret_cast<const float4*>(cb + k*DD);
            float s = 0.f;
#pragma unroll
            for (int i = 0; i < D4/32; i++) {
                float4 a4 = row4[lane + 32*i], w = ws4[lane + 32*i];
                s = fmaf(a4.x, w.x, s); s = fmaf(a4.y, w.y, s);
                s = fmaf(a4.z, w.z, s); s = fmaf(a4.w, w.w, s);
            }
#pragma unroll
            for (int o = 16; o; o >>= 1) s += __shfl_xor_sync(0xffffffffu, s, o);
            if (lane == 0) ss[k] = s;
        }
        __syncthreads();

        // online softmax update (warp 0)
        if (warp == 0) {
            float s = (lane < SUB) ? ss[lane] : -CUDART_INF_F;
            float m = s;
#pragma unroll
            for (int o = 16; o; o >>= 1) m = fmaxf(m, __shfl_xor_sync(0xffffffffu, m, o));
            float mold = ml[0];
            float mnew = fmaxf(mold, m);
            float p = __expf(s - mnew);
            if (lane < SUB) ps[lane] = p;
            float sum = p;
#pragma unroll
            for (int o = 16; o; o >>= 1) sum += __shfl_xor_sync(0xffffffffu, sum, o);
            if (lane == 0) {
                float scale = __expf(mold - mnew);   // exp(-inf)=0 on first chunk
                ml[1] = ml[1]*scale + sum;
                ml[0] = mnew;
                ml[2] = scale;
            }
        }
        __syncthreads();

        // weighted V accumulation: threads 0..191, float4 per thread
        if (tid < D4) {
            float scale = ml[2];
            acc.x *= scale; acc.y *= scale; acc.z *= scale; acc.w *= scale;
#pragma unroll
            for (int k = 0; k < SUB; k++) {
                float p = ps[k];
                float4 v = cb4[k*D4 + tid];
                acc.x = fmaf(p, v.x, acc.x);
                acc.y = fmaf(p, v.y, acc.y);
                acc.z = fmaf(p, v.z, acc.z);
                acc.w = fmaf(p, v.w, acc.w);
            }
        }
        __syncthreads();   // buffer reuse safety before next issue
    }

    int cidx = b*NCH + ch;
    if (tid < D4)
        reinterpret_cast<float4*>(g_pacc)[cidx*D4 + tid] = acc;
    if (tid == 0) { g_pm[cidx] = ml[0]; g_pl[cidx] = ml[1]; }

    // ---- fused combine: last chunk-block for this b folds partials -> g_vin ----
    __threadfence();
    __syncthreads();
    __shared__ int s_last;
    if (tid == 0) s_last = (atomicAdd(&g_cnt_a[b], 1) == NCH-1);
    __syncthreads();
    if (s_last) {
        if (tid == 0) {
            g_cnt_a[b] = 0;
            __threadfence();
            float M = -CUDART_INF_F;
#pragma unroll
            for (int c = 0; c < NCH; c++) M = fmaxf(M, g_pm[b*NCH + c]);
            float L = 0.f;
#pragma unroll
            for (int c = 0; c < NCH; c++) {
                float fc = __expf(g_pm[b*NCH + c] - M);
                ss[c] = fc;
                L += g_pl[b*NCH + c] * fc;
            }
            ss[NCH] = 1.0f / L;
        }
        __syncthreads();
        if (tid < D4) {
            float invL = ss[NCH];
            float4 v = make_float4(0.f,0.f,0.f,0.f);
#pragma unroll
            for (int c = 0; c < NCH; c++) {
                float fc = ss[c];
                float4 a4 = reinterpret_cast<const float4*>(g_pacc)[(b*NCH + c)*D4 + tid];
                v.x = fmaf(a4.x, fc, v.x); v.y = fmaf(a4.y, fc, v.y);
                v.z = fmaf(a4.z, fc, v.z); v.w = fmaf(a4.w, fc, v.w);
            }
            v.x *= invL; v.y *= invL; v.z *= invL; v.w *= invL;
            reinterpret_cast<float4*>(g_vin)[b*D4 + tid] = v;
        }
    }
}

// ---------------- K5: out[b,e] = v_in[b,:]·Wv[e,:] + bv[e] ----------------
__global__ void k_out(const float* __restrict__ Wv, const float* __restrict__ bv,
                      float* __restrict__ out) {
    int e = blockIdx.x;
    __shared__ float wrow[DD];
    for (int i = threadIdx.x; i < D4; i += 128)
        reinterpret_cast<float4*>(wrow)[i] =
            reinterpret_cast<const float4*>(Wv + (size_t)e*DD)[i];
    __syncthreads();
    int warp = threadIdx.x >> 5, lane = threadIdx.x & 31;
    float bve = bv[e];
    const float4* w4 = reinterpret_cast<const float4*>(wrow);
    for (int b = warp; b < BB; b += 4) {
        const float4* v4 = reinterpret_cast<const float4*>(g_vin + b*DD);
        float acc = 0.f;
#pragma unroll
        for (int i = 0; i < D4/32; i++) {
            float4 w = w4[lane + 32*i], v = v4[lane + 32*i];
            acc = fmaf(w.x, v.x, acc); acc = fmaf(w.y, v.y, acc);
            acc = fmaf(w.z, v.z, acc); acc = fmaf(w.w, v.w, acc);
        }
#pragma unroll
        for (int o = 16; o; o >>= 1) acc += __shfl_xor_sync(0xffffffffu, acc, o);
        if (lane == 0) out[b*DD + e] = acc + bve;
    }
}

extern "C" void kernel_launch(void* const* d_in, const int* in_sizes, int n_in,
                              void* d_out, int out_size) {
    const float* sr = (const float*)d_in[0];   // sentence_rep [32,512,768]
    const float* cr = (const float*)d_in[1];   // comment_rep  [32,2048,768]
    const float* Wq = (const float*)d_in[2];
    const float* bq = (const float*)d_in[3];
    const float* Wk = (const float*)d_in[4];
    // d_in[5] = bk — exactly cancels in softmax, unused
    const float* Wv = (const float*)d_in[6];
    const float* bv = (const float*)d_in[7];
    float* out = (float*)d_out;

    k_ssum<<<dim3(NQC, BB), D4>>>(sr);
    k_qsum<<<DD, 128>>>(Wq, bq);
    k_w<<<dim3(BB/2, ESPL), D4>>>(Wk);

    size_t smem = SMEM_FLOATS * sizeof(float);
    cudaFuncSetAttribute(k_attn, cudaFuncAttributeMaxDynamicSharedMemorySize, (int)smem);
    k_attn<<<dim3(NCH, BB), TPB, smem>>>(cr);

    k_out<<<DD, 128>>>(Wv, bv, out);
}

// round 5
// speedup vs baseline: 1.3456x; 1.3456x over previous
#include <cuda_runtime.h>
#include <cstdint>
#include <math_constants.h>

#define BB   32
#define LQ   512
#define LK   2048
#define DD   768
#define D4   (DD/4)     // 192
#define NQC  16
#define QPC  (LQ/NQC)   // 32
#define RPW  16         // rows (keys) per warp
#define WPB  8          // warps per block
#define RPB  (RPW*WPB)  // 128 rows per block
#define NCH  (LK/RPB)   // 16 chunks per batch
#define TPB  256
#define ESPL 8
#define EPB  (DD/ESPL)  // 96

// scratch (device globals — no allocation allowed)
__device__ float g_sp  [BB*NQC*DD];
__device__ float g_ssum[BB*DD];
__device__ float g_qsum[BB*DD];
__device__ float g_wp  [ESPL*BB*DD];
__device__ float g_pm  [BB*NCH];
__device__ float g_pl  [BB*NCH];
__device__ float g_pacc[BB*NCH*DD];
__device__ float g_vin [BB*DD];

// ---------------- K1: partial row-sums of sentence_rep over q ----------------
__global__ void k_ssum_part(const float* __restrict__ sr) {
    int qc = blockIdx.x, b = blockIdx.y, d = threadIdx.x;
    const float* p = sr + ((size_t)b*LQ + (size_t)qc*QPC)*DD + d;
    float a0 = 0.f, a1 = 0.f;
#pragma unroll
    for (int q = 0; q < QPC; q += 2) {
        a0 += p[(size_t)q*DD];
        a1 += p[(size_t)(q+1)*DD];
    }
    g_sp[(b*NQC + qc)*DD + d] = a0 + a1;
}

// ---------------- K1b: reduce partials -> s_sum[b,d] ----------------
__global__ void k_ssum_reduce() {
    int b = blockIdx.x, d = threadIdx.x;
    float a = 0.f;
#pragma unroll
    for (int c = 0; c < NQC; c++) a += g_sp[(b*NQC + c)*DD + d];
    g_ssum[b*DD + d] = a;
}

// ---------------- K2: q_sum[b,e] = s_sum[b,:]·Wq[e,:] + 512*bq[e] ----------------
__global__ void k_qsum(const float* __restrict__ Wq, const float* __restrict__ bq) {
    int e = blockIdx.x;
    __shared__ float wrow[DD];
    for (int i = threadIdx.x; i < D4; i += 128)
        reinterpret_cast<float4*>(wrow)[i] =
            reinterpret_cast<const float4*>(Wq + (size_t)e*DD)[i];
    __syncthreads();
    int warp = threadIdx.x >> 5, lane = threadIdx.x & 31;
    float be = 512.0f * bq[e];
    const float4* w4 = reinterpret_cast<const float4*>(wrow);
    for (int b = warp; b < BB; b += 4) {
        const float4* s4 = reinterpret_cast<const float4*>(g_ssum + b*DD);
        float acc = 0.f;
#pragma unroll
        for (int i = 0; i < D4/32; i++) {
            float4 w = w4[lane + 32*i], s = s4[lane + 32*i];
            acc = fmaf(w.x, s.x, acc); acc = fmaf(w.y, s.y, acc);
            acc = fmaf(w.z, s.z, acc); acc = fmaf(w.w, s.w, acc);
        }
#pragma unroll
        for (int o = 16; o; o >>= 1) acc += __shfl_xor_sync(0xffffffffu, acc, o);
        if (lane == 0) g_qsum[b*DD + e] = acc + be;
    }
}

// ---------------- K3: w partials (R3-proven shape) ----------------
// grid = (DD/128, BB/4, ESPL), 128 threads
__global__ void k_w(const float* __restrict__ Wk) {
    int d  = blockIdx.x * 128 + threadIdx.x;
    int b0 = blockIdx.y * 4;
    int e0 = blockIdx.z * EPB;
    __shared__ float qs[4*EPB];
    for (int i = threadIdx.x; i < 4*EPB; i += 128)
        qs[i] = g_qsum[(b0 + i/EPB)*DD + e0 + (i % EPB)];
    __syncthreads();
    float a0 = 0.f, a1 = 0.f, a2 = 0.f, a3 = 0.f;
#pragma unroll 8
    for (int e = 0; e < EPB; e++) {
        float wk = Wk[(size_t)(e0 + e)*DD + d];
        a0 = fmaf(wk, qs[e],         a0);
        a1 = fmaf(wk, qs[EPB   + e], a1);
        a2 = fmaf(wk, qs[2*EPB + e], a2);
        a3 = fmaf(wk, qs[3*EPB + e], a3);
    }
    int z = blockIdx.z;
    g_wp[(z*BB + b0+0)*DD + d] = a0;
    g_wp[(z*BB + b0+1)*DD + d] = a1;
    g_wp[(z*BB + b0+2)*DD + d] = a2;
    g_wp[(z*BB + b0+3)*DD + d] = a3;
}

// ---------------- K4: warp-autonomous scores+softmax+V-sum, no mainloop syncs ---------
// grid = (NCH, BB) = 512 blocks, 256 threads, static smem.
__global__ void __launch_bounds__(TPB) k_attn(const float* __restrict__ cr) {
    int b = blockIdx.y, ch = blockIdx.x;
    int tid = threadIdx.x, warp = tid >> 5, lane = tid & 31;

    __shared__ float s_ws[DD];
    __shared__ float s_acc[WPB][DD];
    __shared__ float s_m[WPB], s_l[WPB];
    __shared__ float s_f[WPB];
    __shared__ float s_L;

    // ws = sum of e-split partials (L2-resident)
    for (int i = tid; i < DD; i += TPB) {
        float a = 0.f;
#pragma unroll
        for (int z = 0; z < ESPL; z++) a += g_wp[(z*BB + b)*DD + i];
        s_ws[i] = a;
    }
    __syncthreads();

    // w into registers: lane covers float4 slots lane+32*i  (dims 4*(lane+32i))
    float4 w[6];
    const float4* ws4 = reinterpret_cast<const float4*>(s_ws);
#pragma unroll
    for (int i = 0; i < 6; i++) w[i] = ws4[lane + 32*i];

    const float4* rbase = reinterpret_cast<const float4*>(cr) +
                          ((size_t)b*LK + (size_t)ch*RPB + (size_t)warp*RPW)*D4;

    float m = -CUDART_INF_F, l = 0.f;
    float4 acc[6];
#pragma unroll
    for (int i = 0; i < 6; i++) acc[i] = make_float4(0.f,0.f,0.f,0.f);

    for (int r = 0; r < RPW; r++) {
        float4 v[6];
        const float4* row = rbase + (size_t)r*D4 + lane;
#pragma unroll
        for (int i = 0; i < 6; i++) v[i] = row[32*i];

        float s = 0.f;
#pragma unroll
        for (int i = 0; i < 6; i++) {
            s = fmaf(v[i].x, w[i].x, s); s = fmaf(v[i].y, w[i].y, s);
            s = fmaf(v[i].z, w[i].z, s); s = fmaf(v[i].w, w[i].w, s);
        }
#pragma unroll
        for (int o = 16; o; o >>= 1) s += __shfl_xor_sync(0xffffffffu, s, o);

        float mnew = fmaxf(m, s);
        float p = __expf(s - mnew);
        if (mnew != m) {                       // warp-uniform branch
            float scale = __expf(m - mnew);    // 0 on first row (m=-inf)
            l *= scale;
#pragma unroll
            for (int i = 0; i < 6; i++) {
                acc[i].x *= scale; acc[i].y *= scale;
                acc[i].z *= scale; acc[i].w *= scale;
            }
            m = mnew;
        }
        l += p;
#pragma unroll
        for (int i = 0; i < 6; i++) {
            acc[i].x = fmaf(p, v[i].x, acc[i].x);
            acc[i].y = fmaf(p, v[i].y, acc[i].y);
            acc[i].z = fmaf(p, v[i].z, acc[i].z);
            acc[i].w = fmaf(p, v[i].w, acc[i].w);
        }
    }

    // per-warp results to smem (same float4-slot layout -> natural dim order)
    if (lane == 0) { s_m[warp] = m; s_l[warp] = l; }
    float4* sa = reinterpret_cast<float4*>(s_acc[warp]);
#pragma unroll
    for (int i = 0; i < 6; i++) sa[lane + 32*i] = acc[i];
    __syncthreads();

    // block combine -> chunk partial
    if (tid == 0) {
        float M = -CUDART_INF_F;
#pragma unroll
        for (int ww = 0; ww < WPB; ww++) M = fmaxf(M, s_m[ww]);
        float L = 0.f;
#pragma unroll
        for (int ww = 0; ww < WPB; ww++) {
            float f = __expf(s_m[ww] - M);
            s_f[ww] = f;
            L += s_l[ww] * f;
        }
        s_L = L;
        int cidx = b*NCH + ch;
        g_pm[cidx] = M; g_pl[cidx] = L;
    }
    __syncthreads();
    if (tid < D4) {
        float4 a = make_float4(0.f,0.f,0.f,0.f);
#pragma unroll
        for (int ww = 0; ww < WPB; ww++) {
            float f = s_f[ww];
            float4 v = reinterpret_cast<const float4*>(s_acc[ww])[tid];
            a.x = fmaf(f, v.x, a.x); a.y = fmaf(f, v.y, a.y);
            a.z = fmaf(f, v.z, a.z); a.w = fmaf(f, v.w, a.w);
        }
        reinterpret_cast<float4*>(g_pacc)[(b*NCH + ch)*D4 + tid] = a;
    }
}

// ---------------- K5a: combine chunk partials -> v_in[b,d] ----------------
__global__ void k_comb() {
    int b = blockIdx.x, tid = threadIdx.x;   // 192 threads
    __shared__ float f[NCH];
    __shared__ float invL;
    if (tid == 0) {
        float M = -CUDART_INF_F;
        for (int c = 0; c < NCH; c++) M = fmaxf(M, g_pm[b*NCH + c]);
        float L = 0.f;
        for (int c = 0; c < NCH; c++) {
            float fc = __expf(g_pm[b*NCH + c] - M);
            f[c] = fc;
            L += g_pl[b*NCH + c] * fc;
        }
        invL = 1.0f / L;
    }
    __syncthreads();
    float4 v = make_float4(0.f, 0.f, 0.f, 0.f);
#pragma unroll
    for (int c = 0; c < NCH; c++) {
        float fc = f[c];
        float4 a = reinterpret_cast<const float4*>(g_pacc)[(b*NCH + c)*D4 + tid];
        v.x = fmaf(a.x, fc, v.x); v.y = fmaf(a.y, fc, v.y);
        v.z = fmaf(a.z, fc, v.z); v.w = fmaf(a.w, fc, v.w);
    }
    v.x *= invL; v.y *= invL; v.z *= invL; v.w *= invL;
    reinterpret_cast<float4*>(g_vin)[b*D4 + tid] = v;
}

// ---------------- K5b: out[b,e] = v_in[b,:]·Wv[e,:] + bv[e] ----------------
__global__ void k_out(const float* __restrict__ Wv, const float* __restrict__ bv,
                      float* __restrict__ out) {
    int e = blockIdx.x;
    __shared__ float wrow[DD];
    for (int i = threadIdx.x; i < D4; i += 128)
        reinterpret_cast<float4*>(wrow)[i] =
            reinterpret_cast<const float4*>(Wv + (size_t)e*DD)[i];
    __syncthreads();
    int warp = threadIdx.x >> 5, lane = threadIdx.x & 31;
    float bve = bv[e];
    const float4* w4 = reinterpret_cast<const float4*>(wrow);
    for (int b = warp; b < BB; b += 4) {
        const float4* v4 = reinterpret_cast<const float4*>(g_vin + b*DD);
        float acc = 0.f;
#pragma unroll
        for (int i = 0; i < D4/32; i++) {
            float4 w = w4[lane + 32*i], v = v4[lane + 32*i];
            acc = fmaf(w.x, v.x, acc); acc = fmaf(w.y, v.y, acc);
            acc = fmaf(w.z, v.z, acc); acc = fmaf(w.w, v.w, acc);
        }
#pragma unroll
        for (int o = 16; o; o >>= 1) acc += __shfl_xor_sync(0xffffffffu, acc, o);
        if (lane == 0) out[b*DD + e] = acc + bve;
    }
}

extern "C" void kernel_launch(void* const* d_in, const int* in_sizes, int n_in,
                              void* d_out, int out_size) {
    const float* sr = (const float*)d_in[0];   // sentence_rep [32,512,768]
    const float* cr = (const float*)d_in[1];   // comment_rep  [32,2048,768]
    const float* Wq = (const float*)d_in[2];
    const float* bq = (const float*)d_in[3];
    const float* Wk = (const float*)d_in[4];
    // d_in[5] = bk — exactly cancels in softmax, unused
    const float* Wv = (const float*)d_in[6];
    const float* bv = (const float*)d_in[7];
    float* out = (float*)d_out;

    k_ssum_part<<<dim3(NQC, BB), DD>>>(sr);
    k_ssum_reduce<<<BB, DD>>>();
    k_qsum<<<DD, 128>>>(Wq, bq);
    k_w<<<dim3(DD/128, BB/4, ESPL), 128>>>(Wk);
    k_attn<<<dim3(NCH, BB), TPB>>>(cr);
    k_comb<<<BB, D4>>>();
    k_out<<<DD, 128>>>(Wv, bv, out);
}

// round 6
// speedup vs baseline: 1.6000x; 1.1890x over previous
#include <cuda_runtime.h>
#include <cstdint>
#include <math_constants.h>

#define BB   32
#define LQ   512
#define LK   2048
#define DD   768
#define D4   (DD/4)     // 192
#define NQC  16
#define QPC  (LQ/NQC)   // 32
#define RPW  32         // rows (keys) per warp
#define WPB  8          // warps per block
#define RPB  (RPW*WPB)  // 256 rows per block
#define NCH  (LK/RPB)   // 8 chunks per batch
#define TPB  256
#define ESPL 16
#define EPB  (DD/ESPL)  // 48

// scratch (device globals — no allocation allowed)
__device__ float g_sp  [BB*NQC*DD];
__device__ float g_ssum[BB*DD];
__device__ float g_qsum[BB*DD];
__device__ float g_wp  [ESPL*BB*DD];
__device__ float g_pm  [BB*NCH];
__device__ float g_pl  [BB*NCH];
__device__ float g_pacc[BB*NCH*DD];
__device__ float g_vin [BB*DD];

// ---------------- K1: partial row-sums of sentence_rep over q ----------------
__global__ void k_ssum_part(const float* __restrict__ sr) {
    int qc = blockIdx.x, b = blockIdx.y, d = threadIdx.x;
    const float* p = sr + ((size_t)b*LQ + (size_t)qc*QPC)*DD + d;
    float a0 = 0.f, a1 = 0.f;
#pragma unroll
    for (int q = 0; q < QPC; q += 2) {
        a0 += p[(size_t)q*DD];
        a1 += p[(size_t)(q+1)*DD];
    }
    g_sp[(b*NQC + qc)*DD + d] = a0 + a1;
}

// ---------------- K1b: reduce partials -> s_sum[b,d] ----------------
__global__ void k_ssum_reduce() {
    int b = blockIdx.x, d = threadIdx.x;
    float a = 0.f;
#pragma unroll
    for (int c = 0; c < NQC; c++) a += g_sp[(b*NQC + c)*DD + d];
    g_ssum[b*DD + d] = a;
}

// ---------------- K2: q_sum[b,e] = s_sum[b,:]·Wq[e,:] + 512*bq[e] ----------------
__global__ void k_qsum(const float* __restrict__ Wq, const float* __restrict__ bq) {
    int e = blockIdx.x;
    __shared__ float wrow[DD];
    for (int i = threadIdx.x; i < D4; i += 128)
        reinterpret_cast<float4*>(wrow)[i] =
            reinterpret_cast<const float4*>(Wq + (size_t)e*DD)[i];
    __syncthreads();
    int warp = threadIdx.x >> 5, lane = threadIdx.x & 31;
    float be = 512.0f * bq[e];
    const float4* w4 = reinterpret_cast<const float4*>(wrow);
    for (int b = warp; b < BB; b += 4) {
        const float4* s4 = reinterpret_cast<const float4*>(g_ssum + b*DD);
        float acc = 0.f;
#pragma unroll
        for (int i = 0; i < D4/32; i++) {
            float4 w = w4[lane + 32*i], s = s4[lane + 32*i];
            acc = fmaf(w.x, s.x, acc); acc = fmaf(w.y, s.y, acc);
            acc = fmaf(w.z, s.z, acc); acc = fmaf(w.w, s.w, acc);
        }
#pragma unroll
        for (int o = 16; o; o >>= 1) acc += __shfl_xor_sync(0xffffffffu, acc, o);
        if (lane == 0) g_qsum[b*DD + e] = acc + be;
    }
}

// ---------------- K3: w partials — EXACT R3 shape (measured 9.1us) ----------------
// grid = (DD/128, BB/2, ESPL) = 1536 blocks, 128 threads
__global__ void k_w(const float* __restrict__ Wk) {
    int d  = blockIdx.x * 128 + threadIdx.x;
    int b0 = blockIdx.y * 2;
    int e0 = blockIdx.z * EPB;
    __shared__ float qs[2*EPB];
    if (threadIdx.x < 2*EPB)
        qs[threadIdx.x] = g_qsum[(b0 + threadIdx.x/EPB)*DD + e0 + (threadIdx.x % EPB)];
    __syncthreads();
    float a0 = 0.f, a1 = 0.f;
#pragma unroll 8
    for (int e = 0; e < EPB; e++) {
        float wk = Wk[(size_t)(e0 + e)*DD + d];
        a0 = fmaf(wk, qs[e],       a0);
        a1 = fmaf(wk, qs[EPB + e], a1);
    }
    int z = blockIdx.z;
    g_wp[(z*BB + b0+0)*DD + d] = a0;
    g_wp[(z*BB + b0+1)*DD + d] = a1;
}

// ---------------- K4: warp-autonomous, 2 rows per iteration, single wave ----------
// grid = (NCH, BB) = 256 blocks, 256 threads.
__global__ void __launch_bounds__(TPB) k_attn(const float* __restrict__ cr) {
    int b = blockIdx.y, ch = blockIdx.x;
    int tid = threadIdx.x, warp = tid >> 5, lane = tid & 31;

    __shared__ float s_ws[DD];
    __shared__ float s_acc[WPB][DD];
    __shared__ float s_m[WPB], s_l[WPB];
    __shared__ float s_f[WPB];

    // ws = sum of e-split partials (L2-resident)
    for (int i = tid; i < DD; i += TPB) {
        float a = 0.f;
#pragma unroll
        for (int z = 0; z < ESPL; z++) a += g_wp[(z*BB + b)*DD + i];
        s_ws[i] = a;
    }
    __syncthreads();

    // w into registers: lane covers float4 slots lane+32*i
    float4 w[6];
    const float4* ws4 = reinterpret_cast<const float4*>(s_ws);
#pragma unroll
    for (int i = 0; i < 6; i++) w[i] = ws4[lane + 32*i];

    const float4* rbase = reinterpret_cast<const float4*>(cr) +
                          ((size_t)b*LK + (size_t)ch*RPB + (size_t)warp*RPW)*D4 + lane;

    float m = -CUDART_INF_F, l = 0.f;
    float4 acc[6];
#pragma unroll
    for (int i = 0; i < 6; i++) acc[i] = make_float4(0.f,0.f,0.f,0.f);

    for (int r = 0; r < RPW; r += 2) {
        float4 v0[6], v1[6];
        const float4* row0 = rbase + (size_t)r*D4;
        const float4* row1 = row0 + D4;
#pragma unroll
        for (int i = 0; i < 6; i++) v0[i] = row0[32*i];
#pragma unroll
        for (int i = 0; i < 6; i++) v1[i] = row1[32*i];

        float s0 = 0.f, s1 = 0.f;
#pragma unroll
        for (int i = 0; i < 6; i++) {
            s0 = fmaf(v0[i].x, w[i].x, s0); s0 = fmaf(v0[i].y, w[i].y, s0);
            s0 = fmaf(v0[i].z, w[i].z, s0); s0 = fmaf(v0[i].w, w[i].w, s0);
            s1 = fmaf(v1[i].x, w[i].x, s1); s1 = fmaf(v1[i].y, w[i].y, s1);
            s1 = fmaf(v1[i].z, w[i].z, s1); s1 = fmaf(v1[i].w, w[i].w, s1);
        }
#pragma unroll
        for (int o = 16; o; o >>= 1) {
            s0 += __shfl_xor_sync(0xffffffffu, s0, o);
            s1 += __shfl_xor_sync(0xffffffffu, s1, o);
        }

        float mnew = fmaxf(m, fmaxf(s0, s1));
        float p0 = __expf(s0 - mnew);
        float p1 = __expf(s1 - mnew);
        if (mnew != m) {                       // warp-uniform branch
            float scale = __expf(m - mnew);    // 0 on first pair (m=-inf)
            l *= scale;
#pragma unroll
            for (int i = 0; i < 6; i++) {
                acc[i].x *= scale; acc[i].y *= scale;
                acc[i].z *= scale; acc[i].w *= scale;
            }
            m = mnew;
        }
        l += p0 + p1;
#pragma unroll
        for (int i = 0; i < 6; i++) {
            acc[i].x = fmaf(p0, v0[i].x, acc[i].x);
            acc[i].y = fmaf(p0, v0[i].y, acc[i].y);
            acc[i].z = fmaf(p0, v0[i].z, acc[i].z);
            acc[i].w = fmaf(p0, v0[i].w, acc[i].w);
            acc[i].x = fmaf(p1, v1[i].x, acc[i].x);
            acc[i].y = fmaf(p1, v1[i].y, acc[i].y);
            acc[i].z = fmaf(p1, v1[i].z, acc[i].z);
            acc[i].w = fmaf(p1, v1[i].w, acc[i].w);
        }
    }

    // per-warp results to smem (same float4-slot layout -> natural dim order)
    if (lane == 0) { s_m[warp] = m; s_l[warp] = l; }
    float4* sa = reinterpret_cast<float4*>(s_acc[warp]);
#pragma unroll
    for (int i = 0; i < 6; i++) sa[lane + 32*i] = acc[i];
    __syncthreads();

    // block combine -> chunk partial
    if (tid == 0) {
        float M = -CUDART_INF_F;
#pragma unroll
        for (int ww = 0; ww < WPB; ww++) M = fmaxf(M, s_m[ww]);
        float L = 0.f;
#pragma unroll
        for (int ww = 0; ww < WPB; ww++) {
            float f = __expf(s_m[ww] - M);
            s_f[ww] = f;
            L += s_l[ww] * f;
        }
        int cidx = b*NCH + ch;
        g_pm[cidx] = M; g_pl[cidx] = L;
    }
    __syncthreads();
    if (tid < D4) {
        float4 a = make_float4(0.f,0.f,0.f,0.f);
#pragma unroll
        for (int ww = 0; ww < WPB; ww++) {
            float f = s_f[ww];
            float4 v = reinterpret_cast<const float4*>(s_acc[ww])[tid];
            a.x = fmaf(f, v.x, a.x); a.y = fmaf(f, v.y, a.y);
            a.z = fmaf(f, v.z, a.z); a.w = fmaf(f, v.w, a.w);
        }
        reinterpret_cast<float4*>(g_pacc)[(b*NCH + ch)*D4 + tid] = a;
    }
}

// ---------------- K5a: combine chunk partials -> v_in[b,d] ----------------
__global__ void k_comb() {
    int b = blockIdx.x, tid = threadIdx.x;   // 192 threads
    __shared__ float f[NCH];
    __shared__ float invL;
    if (tid == 0) {
        float M = -CUDART_INF_F;
        for (int c = 0; c < NCH; c++) M = fmaxf(M, g_pm[b*NCH + c]);
        float L = 0.f;
        for (int c = 0; c < NCH; c++) {
            float fc = __expf(g_pm[b*NCH + c] - M);
            f[c] = fc;
            L += g_pl[b*NCH + c] * fc;
        }
        invL = 1.0f / L;
    }
    __syncthreads();
    float4 v = make_float4(0.f, 0.f, 0.f, 0.f);
#pragma unroll
    for (int c = 0; c < NCH; c++) {
        float fc = f[c];
        float4 a = reinterpret_cast<const float4*>(g_pacc)[(b*NCH + c)*D4 + tid];
        v.x = fmaf(a.x, fc, v.x); v.y = fmaf(a.y, fc, v.y);
        v.z = fmaf(a.z, fc, v.z); v.w = fmaf(a.w, fc, v.w);
    }
    v.x *= invL; v.y *= invL; v.z *= invL; v.w *= invL;
    reinterpret_cast<float4*>(g_vin)[b*D4 + tid] = v;
}

// ---------------- K5b: out[b,e] = v_in[b,:]·Wv[e,:] + bv[e] ----------------
__global__ void k_out(const float* __restrict__ Wv, const float* __restrict__ bv,
                      float* __restrict__ out) {
    int e = blockIdx.x;
    __shared__ float wrow[DD];
    for (int i = threadIdx.x; i < D4; i += 128)
        reinterpret_cast<float4*>(wrow)[i] =
            reinterpret_cast<const float4*>(Wv + (size_t)e*DD)[i];
    __syncthreads();
    int warp = threadIdx.x >> 5, lane = threadIdx.x & 31;
    float bve = bv[e];
    const float4* w4 = reinterpret_cast<const float4*>(wrow);
    for (int b = warp; b < BB; b += 4) {
        const float4* v4 = reinterpret_cast<const float4*>(g_vin + b*DD);
        float acc = 0.f;
#pragma unroll
        for (int i = 0; i < D4/32; i++) {
            float4 w = w4[lane + 32*i], v = v4[lane + 32*i];
            acc = fmaf(w.x, v.x, acc); acc = fmaf(w.y, v.y, acc);
            acc = fmaf(w.z, v.z, acc); acc = fmaf(w.w, v.w, acc);
        }
#pragma unroll
        for (int o = 16; o; o >>= 1) acc += __shfl_xor_sync(0xffffffffu, acc, o);
        if (lane == 0) out[b*DD + e] = acc + bve;
    }
}

extern "C" void kernel_launch(void* const* d_in, const int* in_sizes, int n_in,
                              void* d_out, int out_size) {
    const float* sr = (const float*)d_in[0];   // sentence_rep [32,512,768]
    const float* cr = (const float*)d_in[1];   // comment_rep  [32,2048,768]
    const float* Wq = (const float*)d_in[2];
    const float* bq = (const float*)d_in[3];
    const float* Wk = (const float*)d_in[4];
    // d_in[5] = bk — exactly cancels in softmax, unused
    const float* Wv = (const float*)d_in[6];
    const float* bv = (const float*)d_in[7];
    float* out = (float*)d_out;

    k_ssum_part<<<dim3(NQC, BB), DD>>>(sr);
    k_ssum_reduce<<<BB, DD>>>();
    k_qsum<<<DD, 128>>>(Wq, bq);
    k_w<<<dim3(DD/128, BB/2, ESPL), 128>>>(Wk);
    k_attn<<<dim3(NCH, BB), TPB>>>(cr);
    k_comb<<<BB, D4>>>();
    k_out<<<DD, 128>>>(Wv, bv, out);
}